// round 4
// baseline (speedup 1.0000x reference)
#include <cuda_runtime.h>
#include <math.h>

#define Bb 16
#define Ff 128
#define Nn 2048
#define BN (Bb*Nn)          // 32768
#define TOT (Bb*Ff*Nn)      // 4194304

// scratch (allocation-free: __device__ globals)
__device__ float  g_s[BN];
__device__ float  g_E[BN];
__device__ double g_sum   = 0.0;
__device__ double g_sumsq = 0.0;

// ---------------------------------------------------------------------------
// Pass 1: s[b,n] = sum_f v[f]*emb[b,f,n]; accumulate global sum / sumsq.
// Block = 256 threads = 16 f-chunks (8 f each) x 16 n-float4 (64 n).
// Per thread: 8 float4 loads (128B in flight). Grid = 512.
// ---------------------------------------------------------------------------
__global__ void __launch_bounds__(256) k_fused(const float* __restrict__ emb,
                                               const float* __restrict__ v) {
    __shared__ float  sv[Ff];
    __shared__ float4 spart[16][16];   // [fc][n4]
    __shared__ float  red_sum[8];
    __shared__ float  red_sq[8];

    int tid = threadIdx.x;
    if (tid < Ff) sv[tid] = v[tid];
    __syncthreads();

    int fc = tid >> 4;                 // 0..15 (8 f each)
    int n4 = tid & 15;                 // 0..15 (float4 of n)
    int b  = blockIdx.x >> 5;          // 0..15
    int ng = blockIdx.x & 31;          // 0..31 (group of 64 n)

    const float4* p = (const float4*)(emb + ((size_t)(b * Ff + fc * 8)) * Nn
                                          + ng * 64) + n4;

    float4 s4 = make_float4(0.f, 0.f, 0.f, 0.f);
    float sum = 0.f, sq = 0.f;
#pragma unroll
    for (int f = 0; f < 8; f++) {
        float4 x = __ldg(p + (size_t)f * (Nn / 4));
        float vf = sv[fc * 8 + f];
        s4.x = fmaf(vf, x.x, s4.x);
        s4.y = fmaf(vf, x.y, s4.y);
        s4.z = fmaf(vf, x.z, s4.z);
        s4.w = fmaf(vf, x.w, s4.w);
        sum += (x.x + x.y) + (x.z + x.w);
        sq = fmaf(x.x, x.x, sq);
        sq = fmaf(x.y, x.y, sq);
        sq = fmaf(x.z, x.z, sq);
        sq = fmaf(x.w, x.w, sq);
    }
    spart[fc][n4] = s4;
    __syncthreads();

    // tree reduce over fc
#pragma unroll
    for (int st = 8; st > 0; st >>= 1) {
        if (fc < st) {
            float4 a = spart[fc][n4];
            float4 c = spart[fc + st][n4];
            a.x += c.x; a.y += c.y; a.z += c.z; a.w += c.w;
            spart[fc][n4] = a;
        }
        __syncthreads();
    }
    if (fc == 0)
        ((float4*)(g_s + (size_t)b * Nn + ng * 64))[n4] = spart[0][n4];

    // block reduce sum & sq -> double atomics
    int lane = tid & 31;
    int wid  = tid >> 5;
#pragma unroll
    for (int o = 16; o > 0; o >>= 1) {
        sum += __shfl_xor_sync(0xffffffffu, sum, o);
        sq  += __shfl_xor_sync(0xffffffffu, sq, o);
    }
    if (lane == 0) { red_sum[wid] = sum; red_sq[wid] = sq; }
    __syncthreads();
    if (wid == 0) {
        float rs = (lane < 8) ? red_sum[lane] : 0.f;
        float rq = (lane < 8) ? red_sq[lane]  : 0.f;
#pragma unroll
        for (int o = 4; o > 0; o >>= 1) {
            rs += __shfl_xor_sync(0xffffffffu, rs, o);
            rq += __shfl_xor_sync(0xffffffffu, rq, o);
        }
        if (lane == 0) {
            atomicAdd(&g_sum, (double)rs);
            atomicAdd(&g_sumsq, (double)rq);
        }
    }
}

// ---------------------------------------------------------------------------
// Pass 2: E[n] = exp(-(s[n]*scale + bias/2)).
// ---------------------------------------------------------------------------
__global__ void __launch_bounds__(256) k_exp(const float* __restrict__ bias) {
    __shared__ float sh_scale, sh_hb;
    if (threadIdx.x == 0) {
        double m   = (double)TOT;
        double var = (g_sumsq - g_sum * g_sum / m) / (m - 1.0);
        sh_scale = (float)(1.0 / sqrt(var));
        sh_hb    = 0.5f * bias[0];
    }
    __syncthreads();
    int idx = blockIdx.x * 256 + threadIdx.x;
    float t = fmaf(g_s[idx], sh_scale, sh_hb);
    g_E[idx] = __expf(-t);
}

// ---------------------------------------------------------------------------
// Pass 3: out[b,i,j] = 1 / (1 + E_i * E_j). 4 rows per block, streaming stores.
// Also re-zeroes the accumulators for the next graph replay.
// ---------------------------------------------------------------------------
__device__ __forceinline__ float frcp(float x) {
    float r;
    asm("rcp.approx.f32 %0, %1;" : "=f"(r) : "f"(x));
    return r;
}

__global__ void __launch_bounds__(512) k_main(float* __restrict__ out) {
    int r0 = blockIdx.x << 2;          // first of 4 rows
    int b  = r0 >> 11;

    const float4* Erow = (const float4*)(g_E + (size_t)b * Nn);
    float4 ej = __ldg(Erow + threadIdx.x);

    float p0 = __ldg(g_E + r0);
    float p1 = __ldg(g_E + r0 + 1);
    float p2 = __ldg(g_E + r0 + 2);
    float p3 = __ldg(g_E + r0 + 3);

    float4 o0, o1, o2, o3;
    o0.x = frcp(fmaf(p0, ej.x, 1.f)); o0.y = frcp(fmaf(p0, ej.y, 1.f));
    o0.z = frcp(fmaf(p0, ej.z, 1.f)); o0.w = frcp(fmaf(p0, ej.w, 1.f));
    o1.x = frcp(fmaf(p1, ej.x, 1.f)); o1.y = frcp(fmaf(p1, ej.y, 1.f));
    o1.z = frcp(fmaf(p1, ej.z, 1.f)); o1.w = frcp(fmaf(p1, ej.w, 1.f));
    o2.x = frcp(fmaf(p2, ej.x, 1.f)); o2.y = frcp(fmaf(p2, ej.y, 1.f));
    o2.z = frcp(fmaf(p2, ej.z, 1.f)); o2.w = frcp(fmaf(p2, ej.w, 1.f));
    o3.x = frcp(fmaf(p3, ej.x, 1.f)); o3.y = frcp(fmaf(p3, ej.y, 1.f));
    o3.z = frcp(fmaf(p3, ej.z, 1.f)); o3.w = frcp(fmaf(p3, ej.w, 1.f));

    float4* orow = (float4*)(out + (size_t)r0 * Nn) + threadIdx.x;
    __stcs(orow,              o0);
    __stcs(orow + Nn / 4,     o1);
    __stcs(orow + Nn / 2,     o2);
    __stcs(orow + 3 * Nn / 4, o3);

    if (blockIdx.x == 0 && threadIdx.x == 0) {
        g_sum = 0.0;
        g_sumsq = 0.0;
    }
}

extern "C" void kernel_launch(void* const* d_in, const int* in_sizes, int n_in,
                              void* d_out, int out_size) {
    // inputs: adj_in [B,N,N] (unused), emb_in [B,F,N], v [F], b [1]
    const float* emb  = (const float*)d_in[1];
    const float* v    = (const float*)d_in[2];
    const float* bias = (const float*)d_in[3];
    float* out = (float*)d_out;

    k_fused<<<512, 256>>>(emb, v);
    k_exp<<<BN / 256, 256>>>(bias);
    k_main<<<BN / 4, 512>>>(out);
}

// round 5
// speedup vs baseline: 1.3237x; 1.3237x over previous
#include <cuda_runtime.h>
#include <math.h>

#define Bb 16
#define Ff 128
#define Nn 2048
#define BN (Bb*Nn)          // 32768
#define TOT (Bb*Ff*Nn)      // 4194304

// scratch (allocation-free: __device__ globals)
__device__ float  g_s[BN];
__device__ float  g_E[BN];
__device__ double g_sum   = 0.0;
__device__ double g_sumsq = 0.0;

// ---------------------------------------------------------------------------
// Pass 1: s[b,n] = sum_f v[f]*emb[b,f,n]; accumulate global sum / sumsq.
// Block = 512 threads = 8 f-chunks (16 f each) x 64 n-positions.
// Grid = 512 blocks (16 b x 32 n-groups). 262K threads, 16 loads each.
// ---------------------------------------------------------------------------
__global__ void __launch_bounds__(512) k_fused(const float* __restrict__ emb,
                                               const float* __restrict__ v) {
    __shared__ float sv[Ff];
    __shared__ float spart[512];
    __shared__ float red_sum[16];
    __shared__ float red_sq[16];

    int tid = threadIdx.x;
    if (tid < Ff) sv[tid] = v[tid];
    __syncthreads();

    int b  = blockIdx.x >> 5;          // 0..15
    int ng = blockIdx.x & 31;          // 0..31 (group of 64 n)
    int nl = tid & 63;                 // 0..63
    int fc = tid >> 6;                 // 0..7  (f-chunk of 16)
    int n  = ng * 64 + nl;

    const float* p  = emb + ((size_t)(b * Ff + fc * 16)) * Nn + n;
    const float* pv = sv + fc * 16;

    float s = 0.f, sum = 0.f, sq = 0.f;
#pragma unroll
    for (int f = 0; f < 16; f++) {
        float x = __ldg(p + (size_t)f * Nn);
        s   = fmaf(pv[f], x, s);
        sum += x;
        sq  = fmaf(x, x, sq);
    }
    spart[tid] = s;
    __syncthreads();
    if (tid < 64) {
        float tot = 0.f;
#pragma unroll
        for (int c = 0; c < 8; c++) tot += spart[c * 64 + tid];
        g_s[b * Nn + ng * 64 + tid] = tot;
    }

    // block reduce sum & sq -> double atomics
    int lane = tid & 31;
    int wid  = tid >> 5;
#pragma unroll
    for (int o = 16; o > 0; o >>= 1) {
        sum += __shfl_xor_sync(0xffffffffu, sum, o);
        sq  += __shfl_xor_sync(0xffffffffu, sq, o);
    }
    if (lane == 0) { red_sum[wid] = sum; red_sq[wid] = sq; }
    __syncthreads();
    if (wid == 0) {
        float rs = (lane < 16) ? red_sum[lane] : 0.f;
        float rq = (lane < 16) ? red_sq[lane]  : 0.f;
#pragma unroll
        for (int o = 8; o > 0; o >>= 1) {
            rs += __shfl_xor_sync(0xffffffffu, rs, o);
            rq += __shfl_xor_sync(0xffffffffu, rq, o);
        }
        if (lane == 0) {
            atomicAdd(&g_sum, (double)rs);
            atomicAdd(&g_sumsq, (double)rq);
        }
    }
}

// ---------------------------------------------------------------------------
// Pass 2: E[n] = exp(-(s[n]*scale + bias/2)).
// ---------------------------------------------------------------------------
__global__ void __launch_bounds__(256) k_exp(const float* __restrict__ bias) {
    __shared__ float sh_scale, sh_hb;
    if (threadIdx.x == 0) {
        double m   = (double)TOT;
        double var = (g_sumsq - g_sum * g_sum / m) / (m - 1.0);
        sh_scale = (float)(1.0 / sqrt(var));
        sh_hb    = 0.5f * bias[0];
    }
    __syncthreads();
    int idx = blockIdx.x * 256 + threadIdx.x;
    float t = fmaf(g_s[idx], sh_scale, sh_hb);
    g_E[idx] = __expf(-t);
}

// ---------------------------------------------------------------------------
// Pass 3: out[b,i,j] = 1 / (1 + E_i * E_j). 4 rows per block, plain stores
// (proven fastest: __stcs regressed). Re-zeroes accumulators for next replay.
// ---------------------------------------------------------------------------
__device__ __forceinline__ float frcp(float x) {
    float r;
    asm("rcp.approx.f32 %0, %1;" : "=f"(r) : "f"(x));
    return r;
}

__global__ void __launch_bounds__(512) k_main(float* __restrict__ out) {
    int r0 = blockIdx.x << 2;          // first of 4 rows
    int b  = r0 >> 11;

    const float4* Erow = (const float4*)(g_E + (size_t)b * Nn);
    float4 ej = __ldg(Erow + threadIdx.x);

    float p0 = __ldg(g_E + r0);
    float p1 = __ldg(g_E + r0 + 1);
    float p2 = __ldg(g_E + r0 + 2);
    float p3 = __ldg(g_E + r0 + 3);

    float4 o0, o1, o2, o3;
    o0.x = frcp(fmaf(p0, ej.x, 1.f)); o0.y = frcp(fmaf(p0, ej.y, 1.f));
    o0.z = frcp(fmaf(p0, ej.z, 1.f)); o0.w = frcp(fmaf(p0, ej.w, 1.f));
    o1.x = frcp(fmaf(p1, ej.x, 1.f)); o1.y = frcp(fmaf(p1, ej.y, 1.f));
    o1.z = frcp(fmaf(p1, ej.z, 1.f)); o1.w = frcp(fmaf(p1, ej.w, 1.f));
    o2.x = frcp(fmaf(p2, ej.x, 1.f)); o2.y = frcp(fmaf(p2, ej.y, 1.f));
    o2.z = frcp(fmaf(p2, ej.z, 1.f)); o2.w = frcp(fmaf(p2, ej.w, 1.f));
    o3.x = frcp(fmaf(p3, ej.x, 1.f)); o3.y = frcp(fmaf(p3, ej.y, 1.f));
    o3.z = frcp(fmaf(p3, ej.z, 1.f)); o3.w = frcp(fmaf(p3, ej.w, 1.f));

    float4* orow = (float4*)(out + (size_t)r0 * Nn) + threadIdx.x;
    orow[0]          = o0;
    orow[Nn / 4]     = o1;
    orow[Nn / 2]     = o2;
    orow[3 * Nn / 4] = o3;

    if (blockIdx.x == 0 && threadIdx.x == 0) {
        g_sum = 0.0;
        g_sumsq = 0.0;
    }
}

extern "C" void kernel_launch(void* const* d_in, const int* in_sizes, int n_in,
                              void* d_out, int out_size) {
    // inputs: adj_in [B,N,N] (unused), emb_in [B,F,N], v [F], b [1]
    const float* emb  = (const float*)d_in[1];
    const float* v    = (const float*)d_in[2];
    const float* bias = (const float*)d_in[3];
    float* out = (float*)d_out;

    k_fused<<<512, 512>>>(emb, v);
    k_exp<<<BN / 256, 256>>>(bias);
    k_main<<<BN / 4, 512>>>(out);
}